// round 12
// baseline (speedup 1.0000x reference)
#include <cuda_runtime.h>
#include <cuda_bf16.h>
#include <mma.h>
#include <math.h>
#include <stdint.h>

using namespace nvcuda;

// ---------------- problem constants ----------------
#define N_DIM 121
#define K_RAW 242
#define KP    256            // padded K (16 wmma k-steps)
#define LDA   264            // smem leading dim in bf16 elems (k-stride), conflict-padded
#define BM    64             // rows per block tile
#define BNF   128            // full N (padded)
#define B_MAX 32768

__device__ float g_scratch[2][B_MAX * N_DIM];

__device__ __forceinline__ float safe_ld(const float* p, long long idx, long long sz) {
    return (p != nullptr && idx >= 0 && idx < sz) ? p[idx] : 0.f;
}

// ---------------- smem layout (bytes) ----------------
// W_hi[128][LDA] | W_lo[128][LDA] | A_hi[64][LDA] | A_lo[64][LDA] | bias[128]
// C buffer (64x128 f32 = 32768B) reuses the A_hi region after compute.
#define W_BYTES (128 * LDA * 2)
#define A_BYTES (BM * LDA * 2)
#define OFF_WHI 0
#define OFF_WLO (OFF_WHI + W_BYTES)
#define OFF_AHI (OFF_WLO + W_BYTES)
#define OFF_ALO (OFF_AHI + A_BYTES)
#define OFF_BIAS (OFF_ALO + A_BYTES)
#define SMEM_TOTAL (OFF_BIAS + 128 * 4)

// ---------------- WMMA gate GEMM + sigmoid ----------------
// g[b,n] = sigmoid( [z|v][b,:] @ [W|U][n,:]^T + bW[n]+bU[n] );  blockIdx.y = plane
extern "C" __global__ void __launch_bounds__(256, 1)
gate_gemm_wmma(const float* __restrict__ z_r, const float* __restrict__ v_r,
               const float* __restrict__ Wr,  const float* __restrict__ Wrb,
               const float* __restrict__ Ur,  const float* __restrict__ Urb,
               const float* __restrict__ z_i, const float* __restrict__ v_i,
               const float* __restrict__ Wi,  const float* __restrict__ Wib,
               const float* __restrict__ Ui,  const float* __restrict__ Uib,
               long long sz_zv, long long sz_w, long long sz_b, int Brows)
{
    extern __shared__ char smem[];
    __nv_bfloat16* Whi = reinterpret_cast<__nv_bfloat16*>(smem + OFF_WHI);
    __nv_bfloat16* Wlo = reinterpret_cast<__nv_bfloat16*>(smem + OFF_WLO);
    __nv_bfloat16* Ahi = reinterpret_cast<__nv_bfloat16*>(smem + OFF_AHI);
    __nv_bfloat16* Alo = reinterpret_cast<__nv_bfloat16*>(smem + OFF_ALO);
    float*         Bia = reinterpret_cast<float*>(smem + OFF_BIAS);
    float*         Cbf = reinterpret_cast<float*>(smem + OFF_AHI);  // reused post-compute

    const int plane = blockIdx.y;
    const float* Z  = plane ? z_i : z_r;
    const float* V  = plane ? v_i : v_r;
    const float* W  = plane ? Wi  : Wr;
    const float* U  = plane ? Ui  : Ur;
    const float* Wb = plane ? Wib : Wrb;
    const float* Ub = plane ? Uib : Urb;

    const int tid  = threadIdx.x;
    const int row0 = blockIdx.x * BM;

    // --- stage weights: [n][k] = W[n,k] | U[n,k-121] | 0, bf16 hi/lo split ---
    for (int idx = tid; idx < 128 * KP; idx += 256) {
        int n = idx >> 8;
        int k = idx & 255;
        float val = 0.f;
        if (n < N_DIM) {
            if (k < N_DIM)      val = safe_ld(W, (long long)n * N_DIM + k, sz_w);
            else if (k < K_RAW) val = safe_ld(U, (long long)n * N_DIM + (k - N_DIM), sz_w);
        }
        __nv_bfloat16 h = __float2bfloat16(val);
        __nv_bfloat16 l = __float2bfloat16(val - __bfloat162float(h));
        Whi[n * LDA + k] = h;
        Wlo[n * LDA + k] = l;
    }
    // --- stage A tile: [r][k] = z[row,k] | v[row,k-121] | 0, bf16 hi/lo ---
    for (int idx = tid; idx < BM * KP; idx += 256) {
        int r = idx >> 8;
        int k = idx & 255;
        long long row = row0 + r;
        float val = 0.f;
        if (row < Brows) {
            if (k < N_DIM)      val = safe_ld(Z, row * N_DIM + k, sz_zv);
            else if (k < K_RAW) val = safe_ld(V, row * N_DIM + (k - N_DIM), sz_zv);
        }
        __nv_bfloat16 h = __float2bfloat16(val);
        __nv_bfloat16 l = __float2bfloat16(val - __bfloat162float(h));
        Ahi[r * LDA + k] = h;
        Alo[r * LDA + k] = l;
    }
    if (tid < 128)
        Bia[tid] = (tid < N_DIM)
                     ? (safe_ld(Wb, tid, sz_b) + safe_ld(Ub, tid, sz_b)) : 0.f;
    __syncthreads();

    // --- compute: 8 warps, 2m x 4n, each 2x2 wmma tiles (32x32) ---
    const int wid = tid >> 5;
    const int wm  = wid & 1;    // 0..1 -> rows 32*wm
    const int wn  = wid >> 1;   // 0..3 -> cols 32*wn

    wmma::fragment<wmma::accumulator, 16, 16, 16, float> c[2][2];
#pragma unroll
    for (int i = 0; i < 2; ++i)
#pragma unroll
        for (int j = 0; j < 2; ++j)
            wmma::fill_fragment(c[i][j], 0.f);

#pragma unroll
    for (int pass = 0; pass < 3; ++pass) {
        const __nv_bfloat16* Ap = (pass == 1) ? Alo : Ahi;
        const __nv_bfloat16* Bp = (pass == 2) ? Wlo : Whi;
#pragma unroll 4
        for (int ks = 0; ks < 16; ++ks) {
            int k0 = ks * 16;
            wmma::fragment<wmma::matrix_a, 16, 16, 16, __nv_bfloat16, wmma::row_major> a[2];
            wmma::fragment<wmma::matrix_b, 16, 16, 16, __nv_bfloat16, wmma::col_major> b[2];
#pragma unroll
            for (int i = 0; i < 2; ++i)
                wmma::load_matrix_sync(a[i], Ap + (wm * 32 + i * 16) * LDA + k0, LDA);
#pragma unroll
            for (int j = 0; j < 2; ++j)
                wmma::load_matrix_sync(b[j], Bp + (wn * 32 + j * 16) * LDA + k0, LDA);
#pragma unroll
            for (int i = 0; i < 2; ++i)
#pragma unroll
                for (int j = 0; j < 2; ++j)
                    wmma::mma_sync(c[i][j], a[i], b[j], c[i][j]);
        }
    }

    __syncthreads();   // all mma done before overwriting A region with C

#pragma unroll
    for (int i = 0; i < 2; ++i)
#pragma unroll
        for (int j = 0; j < 2; ++j)
            wmma::store_matrix_sync(Cbf + (wm * 32 + i * 16) * BNF + wn * 32 + j * 16,
                                    c[i][j], BNF, wmma::mem_row_major);
    __syncthreads();

    // --- epilogue: bias + sigmoid -> g_scratch ---
    float* gdst = g_scratch[plane];
    for (int idx = tid; idx < BM * BNF; idx += 256) {
        int r = idx >> 7;
        int n = idx & 127;
        long long row = row0 + r;
        if (row < Brows && n < N_DIM) {
            float t = Cbf[idx] + Bia[n];
            gdst[row * N_DIM + n] = 1.f / (1.f + __expf(-t));
        }
    }
}

// ---------------- fused complex epilogue kernel ----------------
// Output: six BN-float planes: [x_re][z_re][v_re][x_im][z_im][v_im]
extern "C" __global__ void __launch_bounds__(256)
fuse_kernel(const float* __restrict__ ayr, const float* __restrict__ ayi,
            const float* __restrict__ zr,  const float* __restrict__ zi,
            const float* __restrict__ vr,  const float* __restrict__ vi,
            const float* __restrict__ wdr, const float* __restrict__ wdi,
            const float* __restrict__ raw_eta,
            float* __restrict__ out, int BN,
            long long sz_eta, long long out_floats)
{
    int idx = blockIdx.x * blockDim.x + threadIdx.x;
    if (idx >= BN) return;

    float re  = safe_ld(raw_eta, 0, sz_eta);
    float eta = fmaxf(re, 0.f) + log1pf(__expf(-fabsf(re)));

    int n = idx % N_DIM;

    float zpr = zr[idx], zpi = zi[idx];
    float vpr = vr[idx], vpi = vi[idx];

    float nr = ayr[idx] + eta * (zpr - vpr);
    float ni = ayi[idx] + eta * (zpi - vpi);
    float dr = wdr[n] + eta;
    float di = wdi[n];
    float inv = 1.f / (dr * dr + di * di);
    float xr = (nr * dr + ni * di) * inv;
    float xi = (ni * dr - nr * di) * inv;

    float ur = xr + vpr;
    float ui = xi + vpi;

    float gr = g_scratch[0][idx];
    float gi = g_scratch[1][idx];

    float zor = gr * ur - gi * ui + (1.f - gr) * zpr + gi * zpi;
    float zoi = gr * ui + gi * ur + (1.f - gr) * zpi - gi * zpr;

    float vor = vpr + xr - zor;
    float voi = vpi + xi - zoi;

    float res[6] = {xr, zor, vor, xi, zoi, voi};
#pragma unroll
    for (int p = 0; p < 6; ++p) {
        long long fi = (long long)p * BN + idx;
        if (fi < out_floats) out[fi] = res[p];
    }
}

// ---------------- launch ----------------
extern "C" void kernel_launch(void* const* d_in, const int* in_sizes, int n_in,
                              void* d_out, int out_size)
{
    const float* P[17];
    long long    S[17];
    for (int i = 0; i < 17; ++i) {
        P[i] = (i < n_in) ? (const float*)d_in[i] : nullptr;
        S[i] = (i < n_in) ? (long long)in_sizes[i] : 0;
    }
    const float *ayr = P[0],  *ayi = P[1];
    const float *zr  = P[2],  *zi  = P[3];
    const float *vr  = P[4],  *vi  = P[5];
    const float *wdr = P[6],  *wdi = P[7];
    const float *reta= P[8];
    const float *Wrw = P[9],  *Wrb = P[10];
    const float *Urw = P[11], *Urb = P[12];
    const float *Wiw = P[13], *Wib = P[14];
    const float *Uiw = P[15], *Uib = P[16];

    long long BNl = S[0];
    if (BNl > (long long)B_MAX * N_DIM) BNl = (long long)B_MAX * N_DIM;
    int BN = (int)BNl;
    int B  = BN / N_DIM;
    if (B < 1) B = 1;

    int ntiles = (B + BM - 1) / BM;

    cudaFuncSetAttribute(gate_gemm_wmma,
                         cudaFuncAttributeMaxDynamicSharedMemorySize, SMEM_TOTAL);

    dim3 ggrid(ntiles, 2);
    gate_gemm_wmma<<<ggrid, 256, SMEM_TOTAL>>>(
        zr, vr, Wrw, Wrb, Urw, Urb,
        zi, vi, Wiw, Wib, Uiw, Uib,
        S[2], S[9], S[10], B);

    int fblocks = (BN + 255) / 256;
    fuse_kernel<<<fblocks, 256>>>(ayr, ayi, zr, zi, vr, vi, wdr, wdi, reta,
                                  (float*)d_out, BN,
                                  S[8], (long long)out_size);
}

// round 13
// speedup vs baseline: 2.2681x; 2.2681x over previous
#include <cuda_runtime.h>
#include <cuda_bf16.h>
#include <mma.h>
#include <math.h>
#include <stdint.h>

using namespace nvcuda;

// ---------------- problem constants ----------------
#define N_DIM 121
#define K_RAW 242
#define KP    256            // padded K (16 wmma k-steps)
#define LDA   264            // smem leading dim (bf16 elems), conflict-padded
#define BM    32             // rows per tile
#define BNF   128            // padded N
#define B_MAX 32768
#define GRIDX 148

__device__ float g_scratch[2][B_MAX * N_DIM];

__device__ __forceinline__ float safe_ld(const float* p, long long idx, long long sz) {
    return (p != nullptr && idx >= 0 && idx < sz) ? p[idx] : 0.f;
}

// ---------------- smem layout (bytes) ----------------
#define W_BYTES  (128 * LDA * 2)
#define A_BYTES  (BM * LDA * 2)
#define OFF_WHI  0
#define OFF_WLO  (OFF_WHI + W_BYTES)
#define OFF_AHI  (OFF_WLO + W_BYTES)
#define OFF_ALO  (OFF_AHI + A_BYTES)
#define OFF_BIAS (OFF_ALO + A_BYTES)
#define SMEM_TOTAL (OFF_BIAS + 128 * 4)       // 169,472 B

// ---------------- persistent WMMA gate GEMM + sigmoid (one plane) ----------------
// g[b,n] = sigmoid( [z|v][b,:] @ [W|U][n,:]^T + bW[n]+bU[n] )
extern "C" __global__ void __launch_bounds__(256, 1)
gate_gemm_wmma(const float* __restrict__ Z,  const float* __restrict__ V,
               const float* __restrict__ W,  const float* __restrict__ U,
               const float* __restrict__ Wb, const float* __restrict__ Ub,
               long long sz_w, long long sz_b,
               int Brows, int ntiles, int stride, int plane)
{
    extern __shared__ char smem[];
    __nv_bfloat16* Whi = reinterpret_cast<__nv_bfloat16*>(smem + OFF_WHI);
    __nv_bfloat16* Wlo = reinterpret_cast<__nv_bfloat16*>(smem + OFF_WLO);
    __nv_bfloat16* Ahi = reinterpret_cast<__nv_bfloat16*>(smem + OFF_AHI);
    __nv_bfloat16* Alo = reinterpret_cast<__nv_bfloat16*>(smem + OFF_ALO);
    float*         Bia = reinterpret_cast<float*>(smem + OFF_BIAS);
    float*         Cbf = reinterpret_cast<float*>(smem + OFF_AHI);   // aliases dead A

    const int tid = threadIdx.x;

    // --- stage weights ONCE per block: [n][k] = W|U, bf16 hi/lo split ---
    for (int idx = tid; idx < 128 * KP; idx += 256) {
        int n = idx >> 8;
        int k = idx & 255;
        float val = 0.f;
        if (n < N_DIM) {
            if (k < N_DIM)      val = safe_ld(W, (long long)n * N_DIM + k, sz_w);
            else if (k < K_RAW) val = safe_ld(U, (long long)n * N_DIM + (k - N_DIM), sz_w);
        }
        __nv_bfloat16 h = __float2bfloat16(val);
        __nv_bfloat16 l = __float2bfloat16(val - __bfloat162float(h));
        Whi[n * LDA + k] = h;
        Wlo[n * LDA + k] = l;
    }
    if (tid < 128)
        Bia[tid] = (tid < N_DIM)
                     ? (safe_ld(Wb, tid, sz_b) + safe_ld(Ub, tid, sz_b)) : 0.f;

    const int wid = tid >> 5;
    const int wm  = wid & 1;     // 16-row group
    const int wn  = wid >> 1;    // 32-col group
    const int kth = tid;         // this thread's k column (0..255) for A staging

    // --- register prefetch buffer: rbuf[i] = A[tile*32+i][kth] ---
    float rbuf[BM];
    auto prefetch = [&](int tile) {
#pragma unroll
        for (int i = 0; i < BM; ++i) {
            long long row = (long long)tile * BM + i;
            float v = 0.f;
            if (row < Brows) {
                if (kth < N_DIM)      v = Z[row * N_DIM + kth];
                else if (kth < K_RAW) v = V[row * N_DIM + (kth - N_DIM)];
            }
            rbuf[i] = v;
        }
    };

    float* gdst = g_scratch[plane];
    int t = blockIdx.x;
    if (t < ntiles) prefetch(t);
    __syncthreads();   // weights + bias visible

    for (; t < ntiles; t += stride) {
        // convert prefetched A -> smem bf16 hi/lo
#pragma unroll
        for (int i = 0; i < BM; ++i) {
            float v = rbuf[i];
            __nv_bfloat16 h = __float2bfloat16(v);
            __nv_bfloat16 l = __float2bfloat16(v - __bfloat162float(h));
            Ahi[i * LDA + kth] = h;
            Alo[i * LDA + kth] = l;
        }
        __syncthreads();

        // issue next tile's LDGs now; latency hidden behind the mma loop
        if (t + stride < ntiles) prefetch(t + stride);

        // --- mma: 3-term split fused in one k-loop ---
        wmma::fragment<wmma::accumulator, 16, 16, 16, float> c[2];
        wmma::fill_fragment(c[0], 0.f);
        wmma::fill_fragment(c[1], 0.f);
#pragma unroll
        for (int ks = 0; ks < 16; ++ks) {
            int k0 = ks * 16;
            wmma::fragment<wmma::matrix_a, 16, 16, 16, __nv_bfloat16, wmma::row_major> ah, al;
            wmma::load_matrix_sync(ah, Ahi + (wm * 16) * LDA + k0, LDA);
            wmma::load_matrix_sync(al, Alo + (wm * 16) * LDA + k0, LDA);
#pragma unroll
            for (int j = 0; j < 2; ++j) {
                int ncol = wn * 32 + j * 16;
                wmma::fragment<wmma::matrix_b, 16, 16, 16, __nv_bfloat16, wmma::col_major> bh, bl;
                wmma::load_matrix_sync(bh, Whi + ncol * LDA + k0, LDA);
                wmma::load_matrix_sync(bl, Wlo + ncol * LDA + k0, LDA);
                wmma::mma_sync(c[j], ah, bh, c[j]);
                wmma::mma_sync(c[j], al, bh, c[j]);
                wmma::mma_sync(c[j], ah, bl, c[j]);
            }
        }
        __syncthreads();   // all A reads done; safe to alias C onto A region

        wmma::store_matrix_sync(Cbf + (wm * 16) * BNF + wn * 32,      c[0], BNF, wmma::mem_row_major);
        wmma::store_matrix_sync(Cbf + (wm * 16) * BNF + wn * 32 + 16, c[1], BNF, wmma::mem_row_major);
        __syncthreads();

        // --- epilogue: bias + sigmoid -> g_scratch ---
#pragma unroll
        for (int ii = 0; ii < (BM * BNF) / 256; ++ii) {
            int idx = ii * 256 + tid;
            int r = idx >> 7;
            int n = idx & 127;
            long long row = (long long)t * BM + r;
            if (row < Brows && n < N_DIM) {
                float tv = Cbf[idx] + Bia[n];
                gdst[row * N_DIM + n] = 1.f / (1.f + __expf(-tv));
            }
        }
        __syncthreads();   // Cbf reads done before next tile's convert overwrites
    }
}

// ---------------- fused complex epilogue kernel ----------------
// Output: six BN-float planes: [x_re][z_re][v_re][x_im][z_im][v_im]
extern "C" __global__ void __launch_bounds__(256)
fuse_kernel(const float* __restrict__ ayr, const float* __restrict__ ayi,
            const float* __restrict__ zr,  const float* __restrict__ zi,
            const float* __restrict__ vr,  const float* __restrict__ vi,
            const float* __restrict__ wdr, const float* __restrict__ wdi,
            const float* __restrict__ raw_eta,
            float* __restrict__ out, int BN,
            long long sz_eta, long long out_floats)
{
    int idx = blockIdx.x * blockDim.x + threadIdx.x;
    if (idx >= BN) return;

    float re  = safe_ld(raw_eta, 0, sz_eta);
    float eta = fmaxf(re, 0.f) + log1pf(__expf(-fabsf(re)));

    int n = idx % N_DIM;

    float zpr = zr[idx], zpi = zi[idx];
    float vpr = vr[idx], vpi = vi[idx];

    float nr = ayr[idx] + eta * (zpr - vpr);
    float ni = ayi[idx] + eta * (zpi - vpi);
    float dr = wdr[n] + eta;
    float di = wdi[n];
    float inv = 1.f / (dr * dr + di * di);
    float xr = (nr * dr + ni * di) * inv;
    float xi = (ni * dr - nr * di) * inv;

    float ur = xr + vpr;
    float ui = xi + vpi;

    float gr = g_scratch[0][idx];
    float gi = g_scratch[1][idx];

    float zor = gr * ur - gi * ui + (1.f - gr) * zpr + gi * zpi;
    float zoi = gr * ui + gi * ur + (1.f - gr) * zpi - gi * zpr;

    float vor = vpr + xr - zor;
    float voi = vpi + xi - zoi;

    float res[6] = {xr, zor, vor, xi, zoi, voi};
#pragma unroll
    for (int p = 0; p < 6; ++p) {
        long long fi = (long long)p * BN + idx;
        if (fi < out_floats) out[fi] = res[p];
    }
}

// 4th launch so ncu's fixed skip (-s 5) lands on a GEMM launch.
extern "C" __global__ void dummy_probe() {}

// ---------------- launch ----------------
extern "C" void kernel_launch(void* const* d_in, const int* in_sizes, int n_in,
                              void* d_out, int out_size)
{
    const float* P[17];
    long long    S[17];
    for (int i = 0; i < 17; ++i) {
        P[i] = (i < n_in) ? (const float*)d_in[i] : nullptr;
        S[i] = (i < n_in) ? (long long)in_sizes[i] : 0;
    }
    const float *ayr = P[0],  *ayi = P[1];
    const float *zr  = P[2],  *zi  = P[3];
    const float *vr  = P[4],  *vi  = P[5];
    const float *wdr = P[6],  *wdi = P[7];
    const float *reta= P[8];
    const float *Wrw = P[9],  *Wrb = P[10];
    const float *Urw = P[11], *Urb = P[12];
    const float *Wiw = P[13], *Wib = P[14];
    const float *Uiw = P[15], *Uib = P[16];

    long long BNl = S[0];
    if (BNl > (long long)B_MAX * N_DIM) BNl = (long long)B_MAX * N_DIM;
    int BN = (int)BNl;
    int B  = BN / N_DIM;
    if (B < 1) B = 1;

    int ntiles = (B + BM - 1) / BM;
    int gx = (ntiles < GRIDX) ? ntiles : GRIDX;

    cudaFuncSetAttribute(gate_gemm_wmma,
                         cudaFuncAttributeMaxDynamicSharedMemorySize, SMEM_TOTAL);

    gate_gemm_wmma<<<gx, 256, SMEM_TOTAL>>>(zr, vr, Wrw, Urw, Wrb, Urb,
                                            S[9], S[10], B, ntiles, gx, 0);
    gate_gemm_wmma<<<gx, 256, SMEM_TOTAL>>>(zi, vi, Wiw, Uiw, Wib, Uib,
                                            S[9], S[10], B, ntiles, gx, 1);

    int fblocks = (BN + 255) / 256;
    fuse_kernel<<<fblocks, 256>>>(ayr, ayi, zr, zi, vr, vi, wdr, wdi, reta,
                                  (float*)d_out, BN,
                                  S[8], (long long)out_size);

    dummy_probe<<<1, 32>>>();
}

// round 14
// speedup vs baseline: 2.4861x; 1.0961x over previous
#include <cuda_runtime.h>
#include <cuda_bf16.h>
#include <mma.h>
#include <math.h>
#include <stdint.h>

using namespace nvcuda;

// ---------------- problem constants ----------------
#define N_DIM 121
#define K_RAW 242
#define K_BIAS 242           // bias folded in as k-column 242
#define KP    256            // padded K (16 wmma k-steps)
#define LDA   264            // smem leading dim (bf16), conflict-padded
#define BM    64             // rows per tile
#define GPITCH 128           // g_scratch row pitch (floats)
#define B_MAX 32768
#define GRIDX 148

// g scratch, padded rows so wmma can store full 16x16 tiles directly.
__device__ float g_scratch[2][(long long)B_MAX * GPITCH];

__device__ __forceinline__ float safe_ld(const float* p, long long idx, long long sz) {
    return (p != nullptr && idx >= 0 && idx < sz) ? p[idx] : 0.f;
}

// ---------------- smem layout (bytes) ----------------
#define W_BYTES  (128 * LDA * 2)
#define A_BYTES  (BM * LDA * 2)
#define OFF_WHI  0
#define OFF_WLO  (OFF_WHI + W_BYTES)
#define OFF_AHI  (OFF_WLO + W_BYTES)
#define OFF_ALO  (OFF_AHI + A_BYTES)
#define SMEM_TOTAL (OFF_ALO + A_BYTES)        // 202,752 B

// ---------------- persistent WMMA gate GEMM + sigmoid (one plane) ----------------
// g[b,n] = sigmoid( [z|v|1][b,:] @ [W|U|bias][n,:]^T )
extern "C" __global__ void __launch_bounds__(256, 1)
gate_gemm_wmma(const float* __restrict__ Z,  const float* __restrict__ V,
               const float* __restrict__ W,  const float* __restrict__ U,
               const float* __restrict__ Wb, const float* __restrict__ Ub,
               long long sz_w, long long sz_b,
               int Brows, int ntiles, int stride, int plane)
{
    extern __shared__ char smem[];
    __nv_bfloat16* Whi = reinterpret_cast<__nv_bfloat16*>(smem + OFF_WHI);
    __nv_bfloat16* Wlo = reinterpret_cast<__nv_bfloat16*>(smem + OFF_WLO);
    __nv_bfloat16* Ahi = reinterpret_cast<__nv_bfloat16*>(smem + OFF_AHI);
    __nv_bfloat16* Alo = reinterpret_cast<__nv_bfloat16*>(smem + OFF_ALO);

    const int tid = threadIdx.x;

    // --- stage weights ONCE: [n][k] = W | U | bias | 0, bf16 hi/lo split ---
    for (int idx = tid; idx < 128 * KP; idx += 256) {
        int n = idx >> 8;
        int k = idx & 255;
        float val = 0.f;
        if (n < N_DIM) {
            if (k < N_DIM)        val = safe_ld(W, (long long)n * N_DIM + k, sz_w);
            else if (k < K_RAW)   val = safe_ld(U, (long long)n * N_DIM + (k - N_DIM), sz_w);
            else if (k == K_BIAS) val = safe_ld(Wb, n, sz_b) + safe_ld(Ub, n, sz_b);
        }
        __nv_bfloat16 h = __float2bfloat16(val);
        __nv_bfloat16 l = __float2bfloat16(val - __bfloat162float(h));
        Whi[n * LDA + k] = h;
        Wlo[n * LDA + k] = l;
    }
    // zero the pad k-columns of A once (243..255 never rewritten; 242 set below)
    for (int idx = tid; idx < BM; idx += 256) {
        for (int k = K_RAW; k < KP; ++k) {
            Ahi[idx * LDA + k] = __float2bfloat16(0.f);
            Alo[idx * LDA + k] = __float2bfloat16(0.f);
        }
    }

    const int wid = tid >> 5;
    const int wm  = wid & 3;     // 4 groups of 16 rows
    const int wn  = wid >> 2;    // 2 groups of 64 cols
    const int kth = tid;         // this thread's k column for A staging

    // --- register prefetch: rbuf[i] = A[tile*64+i][kth] ---
    float rbuf[BM];
    auto prefetch = [&](int tile) {
        if (kth >= K_RAW) return;
        const float* src  = (kth < N_DIM) ? Z : V;
        const int    koff = (kth < N_DIM) ? kth : (kth - N_DIM);
#pragma unroll
        for (int i = 0; i < BM; ++i) {
            long long row = (long long)tile * BM + i;
            rbuf[i] = (row < Brows) ? src[row * N_DIM + koff] : 0.f;
        }
    };

    float* gdst = g_scratch[plane];
    int t = blockIdx.x;
    if (t < ntiles) prefetch(t);
    __syncthreads();   // weights + A-pad visible

    for (; t < ntiles; t += stride) {
        // convert prefetched A -> smem bf16 hi/lo (k column kth)
        if (kth < K_RAW) {
#pragma unroll
            for (int i = 0; i < BM; ++i) {
                float v = rbuf[i];
                __nv_bfloat16 h = __float2bfloat16(v);
                __nv_bfloat16 l = __float2bfloat16(v - __bfloat162float(h));
                Ahi[i * LDA + kth] = h;
                Alo[i * LDA + kth] = l;
            }
        } else if (kth == K_BIAS) {
#pragma unroll
            for (int i = 0; i < BM; ++i) {
                Ahi[i * LDA + kth] = __float2bfloat16(1.f);
                Alo[i * LDA + kth] = __float2bfloat16(0.f);
            }
        }
        __syncthreads();

        // issue next tile's LDGs now; latency hidden behind the mma loop
        if (t + stride < ntiles) prefetch(t + stride);

        // --- mma: 3-term bf16 split, 16 k-steps, 1m x 4n tiles per warp ---
        wmma::fragment<wmma::accumulator, 16, 16, 16, float> c[4];
#pragma unroll
        for (int j = 0; j < 4; ++j) wmma::fill_fragment(c[j], 0.f);

#pragma unroll
        for (int ks = 0; ks < 16; ++ks) {
            int k0 = ks * 16;
            wmma::fragment<wmma::matrix_a, 16, 16, 16, __nv_bfloat16, wmma::row_major> ah, al;
            wmma::load_matrix_sync(ah, Ahi + (wm * 16) * LDA + k0, LDA);
            wmma::load_matrix_sync(al, Alo + (wm * 16) * LDA + k0, LDA);
#pragma unroll
            for (int j = 0; j < 4; ++j) {
                int ncol = wn * 64 + j * 16;
                wmma::fragment<wmma::matrix_b, 16, 16, 16, __nv_bfloat16, wmma::col_major> bh, bl;
                wmma::load_matrix_sync(bh, Whi + ncol * LDA + k0, LDA);
                wmma::load_matrix_sync(bl, Wlo + ncol * LDA + k0, LDA);
                wmma::mma_sync(c[j], ah, bh, c[j]);
                wmma::mma_sync(c[j], al, bh, c[j]);
                wmma::mma_sync(c[j], ah, bl, c[j]);
            }
        }

        // --- sigmoid on fragments (elementwise, layout-agnostic), store direct ---
        long long grow0 = (long long)t * BM + wm * 16;
#pragma unroll
        for (int j = 0; j < 4; ++j) {
#pragma unroll
            for (int e = 0; e < c[j].num_elements; ++e)
                c[j].x[e] = 1.f / (1.f + __expf(-c[j].x[e]));
            wmma::store_matrix_sync(gdst + grow0 * GPITCH + wn * 64 + j * 16,
                                    c[j], GPITCH, wmma::mem_row_major);
        }
        __syncthreads();   // all A reads done before next convert overwrites
    }
}

// ---------------- fused complex epilogue kernel ----------------
// Output: six BN-float planes: [x_re][z_re][v_re][x_im][z_im][v_im]
extern "C" __global__ void __launch_bounds__(256)
fuse_kernel(const float* __restrict__ ayr, const float* __restrict__ ayi,
            const float* __restrict__ zr,  const float* __restrict__ zi,
            const float* __restrict__ vr,  const float* __restrict__ vi,
            const float* __restrict__ wdr, const float* __restrict__ wdi,
            const float* __restrict__ raw_eta,
            float* __restrict__ out, int BN,
            long long sz_eta, long long out_floats)
{
    int idx = blockIdx.x * blockDim.x + threadIdx.x;
    if (idx >= BN) return;

    float re  = safe_ld(raw_eta, 0, sz_eta);
    float eta = fmaxf(re, 0.f) + log1pf(__expf(-fabsf(re)));

    unsigned uidx = (unsigned)idx;
    unsigned row  = uidx / N_DIM;
    unsigned n    = uidx - row * N_DIM;

    float zpr = zr[idx], zpi = zi[idx];
    float vpr = vr[idx], vpi = vi[idx];

    float nr = ayr[idx] + eta * (zpr - vpr);
    float ni = ayi[idx] + eta * (zpi - vpi);
    float dr = wdr[n] + eta;
    float di = wdi[n];
    float inv = 1.f / (dr * dr + di * di);
    float xr = (nr * dr + ni * di) * inv;
    float xi = (ni * dr - nr * di) * inv;

    float ur = xr + vpr;
    float ui = xi + vpi;

    long long gidx = (long long)row * GPITCH + n;
    float gr = g_scratch[0][gidx];
    float gi = g_scratch[1][gidx];

    float zor = gr * ur - gi * ui + (1.f - gr) * zpr + gi * zpi;
    float zoi = gr * ui + gi * ur + (1.f - gr) * zpi - gi * zpr;

    float vor = vpr + xr - zor;
    float voi = vpi + xi - zoi;

    float res[6] = {xr, zor, vor, xi, zoi, voi};
#pragma unroll
    for (int p = 0; p < 6; ++p) {
        long long fi = (long long)p * BN + idx;
        if (fi < out_floats) out[fi] = res[p];
    }
}

// ---------------- launch ----------------
extern "C" void kernel_launch(void* const* d_in, const int* in_sizes, int n_in,
                              void* d_out, int out_size)
{
    const float* P[17];
    long long    S[17];
    for (int i = 0; i < 17; ++i) {
        P[i] = (i < n_in) ? (const float*)d_in[i] : nullptr;
        S[i] = (i < n_in) ? (long long)in_sizes[i] : 0;
    }
    const float *ayr = P[0],  *ayi = P[1];
    const float *zr  = P[2],  *zi  = P[3];
    const float *vr  = P[4],  *vi  = P[5];
    const float *wdr = P[6],  *wdi = P[7];
    const float *reta= P[8];
    const float *Wrw = P[9],  *Wrb = P[10];
    const float *Urw = P[11], *Urb = P[12];
    const float *Wiw = P[13], *Wib = P[14];
    const float *Uiw = P[15], *Uib = P[16];

    long long BNl = S[0];
    if (BNl > (long long)B_MAX * N_DIM) BNl = (long long)B_MAX * N_DIM;
    int BN = (int)BNl;
    int B  = BN / N_DIM;
    if (B < 1) B = 1;

    int ntiles = (B + BM - 1) / BM;
    int gx = (ntiles < GRIDX) ? ntiles : GRIDX;

    cudaFuncSetAttribute(gate_gemm_wmma,
                         cudaFuncAttributeMaxDynamicSharedMemorySize, SMEM_TOTAL);

    gate_gemm_wmma<<<gx, 256, SMEM_TOTAL>>>(zr, vr, Wrw, Urw, Wrb, Urb,
                                            S[9], S[10], B, ntiles, gx, 0);
    gate_gemm_wmma<<<gx, 256, SMEM_TOTAL>>>(zi, vi, Wiw, Uiw, Wib, Uib,
                                            S[9], S[10], B, ntiles, gx, 1);

    int fblocks = (BN + 255) / 256;
    fuse_kernel<<<fblocks, 256>>>(ayr, ayi, zr, zi, vr, vi, wdr, wdi, reta,
                                  (float*)d_out, BN,
                                  S[8], (long long)out_size);
}

// round 15
// speedup vs baseline: 3.4163x; 1.3742x over previous
#include <cuda_runtime.h>
#include <cuda_bf16.h>
#include <mma.h>
#include <math.h>
#include <stdint.h>

using namespace nvcuda;

// ---------------- problem constants ----------------
#define N_DIM 121
#define K_RAW 242
#define K_BIAS 242           // bias folded in as k-column 242
#define KP    256            // padded K (16 wmma k-steps)
#define LDA   264            // smem leading dim (bf16), conflict-padded
#define BM    64             // rows per tile
#define GPITCH 128           // g_scratch row pitch (floats)
#define B_MAX 32768
#define GRIDX 148
#define NTHR  512

// g scratch, padded rows so wmma can store 16x16 tiles directly.
__device__ float g_scratch[2][(long long)B_MAX * GPITCH];

__device__ __forceinline__ float safe_ld(const float* p, long long idx, long long sz) {
    return (p != nullptr && idx >= 0 && idx < sz) ? p[idx] : 0.f;
}

// ---------------- smem layout (bytes) ----------------
#define W_BYTES  (128 * LDA * 2)
#define A_BYTES  (BM * LDA * 2)
#define OFF_WHI  0
#define OFF_WLO  (OFF_WHI + W_BYTES)
#define OFF_AHI  (OFF_WLO + W_BYTES)
#define OFF_ALO  (OFF_AHI + A_BYTES)
#define SMEM_TOTAL (OFF_ALO + A_BYTES)        // 202,752 B

// ---------------- persistent WMMA gate GEMM + sigmoid (one plane) ----------------
// g[b,n] = sigmoid( [z|v|1][b,:] @ [W|U|bias][n,:]^T )
extern "C" __global__ void __launch_bounds__(NTHR, 1)
gate_gemm_wmma(const float* __restrict__ Z,  const float* __restrict__ V,
               const float* __restrict__ W,  const float* __restrict__ U,
               const float* __restrict__ Wb, const float* __restrict__ Ub,
               long long sz_w, long long sz_b,
               int Brows, int ntiles, int stride, int plane)
{
    extern __shared__ char smem[];
    __nv_bfloat16* Whi = reinterpret_cast<__nv_bfloat16*>(smem + OFF_WHI);
    __nv_bfloat16* Wlo = reinterpret_cast<__nv_bfloat16*>(smem + OFF_WLO);
    __nv_bfloat16* Ahi = reinterpret_cast<__nv_bfloat16*>(smem + OFF_AHI);
    __nv_bfloat16* Alo = reinterpret_cast<__nv_bfloat16*>(smem + OFF_ALO);

    const int tid = threadIdx.x;

    // --- stage weights ONCE: [n][k] = W | U | bias | 0, bf16 hi/lo split ---
    for (int idx = tid; idx < 128 * KP; idx += NTHR) {
        int n = idx >> 8;
        int k = idx & 255;
        float val = 0.f;
        if (n < N_DIM) {
            if (k < N_DIM)        val = safe_ld(W, (long long)n * N_DIM + k, sz_w);
            else if (k < K_RAW)   val = safe_ld(U, (long long)n * N_DIM + (k - N_DIM), sz_w);
            else if (k == K_BIAS) val = safe_ld(Wb, n, sz_b) + safe_ld(Ub, n, sz_b);
        }
        __nv_bfloat16 h = __float2bfloat16(val);
        __nv_bfloat16 l = __float2bfloat16(val - __bfloat162float(h));
        Whi[n * LDA + k] = h;
        Wlo[n * LDA + k] = l;
    }
    // zero the A pad k-columns once (242..255; 242 overwritten with 1.0 below)
    for (int idx = tid; idx < BM; idx += NTHR) {
        for (int k = K_RAW; k < KP; ++k) {
            Ahi[idx * LDA + k] = __float2bfloat16(0.f);
            Alo[idx * LDA + k] = __float2bfloat16(0.f);
        }
    }

    const int wid  = tid >> 5;
    const int wm   = wid & 3;        // 4 groups of 16 rows
    const int wn   = wid >> 2;       // 4 groups of 32 cols
    const int kcol = tid & 255;      // staged k column
    const int rh   = tid >> 8;       // row half: 0 -> rows 0..31, 1 -> 32..63

    // --- register prefetch: rbuf[i] = A[tile*64 + rh*32 + i][kcol] ---
    float rbuf[32];
    auto prefetch = [&](int tile) {
        if (kcol >= K_RAW) return;
        const float* src  = (kcol < N_DIM) ? Z : V;
        const int    koff = (kcol < N_DIM) ? kcol : (kcol - N_DIM);
#pragma unroll
        for (int i = 0; i < 32; ++i) {
            long long row = (long long)tile * BM + rh * 32 + i;
            rbuf[i] = (row < Brows) ? src[row * N_DIM + koff] : 0.f;
        }
    };

    float* gdst = g_scratch[plane];
    int t = blockIdx.x;
    if (t < ntiles) prefetch(t);
    __syncthreads();   // weights + A-pad visible

    for (; t < ntiles; t += stride) {
        // convert prefetched A -> smem bf16 hi/lo (k column kcol, 32 rows)
        if (kcol < K_RAW) {
#pragma unroll
            for (int i = 0; i < 32; ++i) {
                float v = rbuf[i];
                __nv_bfloat16 h = __float2bfloat16(v);
                __nv_bfloat16 l = __float2bfloat16(v - __bfloat162float(h));
                int r = rh * 32 + i;
                Ahi[r * LDA + kcol] = h;
                Alo[r * LDA + kcol] = l;
            }
        } else if (kcol == K_BIAS) {
#pragma unroll
            for (int i = 0; i < 32; ++i) {
                int r = rh * 32 + i;
                Ahi[r * LDA + kcol] = __float2bfloat16(1.f);
                Alo[r * LDA + kcol] = __float2bfloat16(0.f);
            }
        }
        __syncthreads();

        // issue next tile's LDGs now; latency hidden behind the mma loop
        if (t + stride < ntiles) prefetch(t + stride);

        // --- mma: 3-term bf16 split, 16 k-steps, 1m x 2n per warp ---
        wmma::fragment<wmma::accumulator, 16, 16, 16, float> c[2];
        wmma::fill_fragment(c[0], 0.f);
        wmma::fill_fragment(c[1], 0.f);

#pragma unroll
        for (int ks = 0; ks < 16; ++ks) {
            int k0 = ks * 16;
            wmma::fragment<wmma::matrix_a, 16, 16, 16, __nv_bfloat16, wmma::row_major> ah, al;
            wmma::load_matrix_sync(ah, Ahi + (wm * 16) * LDA + k0, LDA);
            wmma::load_matrix_sync(al, Alo + (wm * 16) * LDA + k0, LDA);
#pragma unroll
            for (int j = 0; j < 2; ++j) {
                int ncol = wn * 32 + j * 16;
                wmma::fragment<wmma::matrix_b, 16, 16, 16, __nv_bfloat16, wmma::col_major> bh, bl;
                wmma::load_matrix_sync(bh, Whi + ncol * LDA + k0, LDA);
                wmma::load_matrix_sync(bl, Wlo + ncol * LDA + k0, LDA);
                wmma::mma_sync(c[j], ah, bh, c[j]);
                wmma::mma_sync(c[j], al, bh, c[j]);
                wmma::mma_sync(c[j], ah, bl, c[j]);
            }
        }

        // --- sigmoid on fragments (layout-agnostic), store direct to g_scratch ---
        long long grow0 = (long long)t * BM + wm * 16;
#pragma unroll
        for (int j = 0; j < 2; ++j) {
#pragma unroll
            for (int e = 0; e < c[j].num_elements; ++e)
                c[j].x[e] = 1.f / (1.f + __expf(-c[j].x[e]));
            wmma::store_matrix_sync(gdst + grow0 * GPITCH + wn * 32 + j * 16,
                                    c[j], GPITCH, wmma::mem_row_major);
        }
        __syncthreads();   // all A reads done before next convert overwrites
    }
}

// ---------------- fused complex epilogue kernel (x4 vectorized) ----------------
// Output: six BN-float planes: [x_re][z_re][v_re][x_im][z_im][v_im]
extern "C" __global__ void __launch_bounds__(256)
fuse_kernel(const float* __restrict__ ayr, const float* __restrict__ ayi,
            const float* __restrict__ zr,  const float* __restrict__ zi,
            const float* __restrict__ vr,  const float* __restrict__ vi,
            const float* __restrict__ wdr, const float* __restrict__ wdi,
            const float* __restrict__ raw_eta,
            float* __restrict__ out, int BN,
            long long sz_eta, long long out_floats)
{
    int q = blockIdx.x * blockDim.x + threadIdx.x;   // quad index
    int nquads = BN >> 2;
    if (q >= nquads) return;
    int idx0 = q << 2;

    float re  = safe_ld(raw_eta, 0, sz_eta);
    float eta = fmaxf(re, 0.f) + log1pf(__expf(-fabsf(re)));

    float4 zr4 = *reinterpret_cast<const float4*>(zr + idx0);
    float4 zi4 = *reinterpret_cast<const float4*>(zi + idx0);
    float4 vr4 = *reinterpret_cast<const float4*>(vr + idx0);
    float4 vi4 = *reinterpret_cast<const float4*>(vi + idx0);
    float4 ar4 = *reinterpret_cast<const float4*>(ayr + idx0);
    float4 ai4 = *reinterpret_cast<const float4*>(ayi + idx0);

    float4 oxr, oxi, ozr, ozi, ovr, ovi;
    float* pzr = &zr4.x; float* pzi = &zi4.x;
    float* pvr = &vr4.x; float* pvi = &vi4.x;
    float* par = &ar4.x; float* pai = &ai4.x;
    float* poxr = &oxr.x; float* poxi = &oxi.x;
    float* pozr = &ozr.x; float* pozi = &ozi.x;
    float* povr = &ovr.x; float* povi = &ovi.x;

#pragma unroll
    for (int e = 0; e < 4; ++e) {
        int idx = idx0 + e;
        unsigned row = (unsigned)idx / N_DIM;
        unsigned n   = (unsigned)idx - row * N_DIM;

        float zpr = pzr[e], zpi = pzi[e];
        float vpr = pvr[e], vpi = pvi[e];

        float nr = par[e] + eta * (zpr - vpr);
        float ni = pai[e] + eta * (zpi - vpi);
        float dr = wdr[n] + eta;
        float di = wdi[n];
        float inv = 1.f / (dr * dr + di * di);
        float xr = (nr * dr + ni * di) * inv;
        float xi = (ni * dr - nr * di) * inv;

        float ur = xr + vpr;
        float ui = xi + vpi;

        long long gidx = (long long)row * GPITCH + n;
        float gr = g_scratch[0][gidx];
        float gi = g_scratch[1][gidx];

        float zor = gr * ur - gi * ui + (1.f - gr) * zpr + gi * zpi;
        float zoi = gr * ui + gi * ur + (1.f - gr) * zpi - gi * zpr;

        poxr[e] = xr;  poxi[e] = xi;
        pozr[e] = zor; pozi[e] = zoi;
        povr[e] = vpr + xr - zor;
        povi[e] = vpi + xi - zoi;
    }

    // guarded vector stores (plane p at float offset p*BN + idx0)
    float4 res[6] = {oxr, ozr, ovr, oxi, ozi, ovi};
#pragma unroll
    for (int p = 0; p < 6; ++p) {
        long long fi = (long long)p * BN + idx0;
        if (fi + 3 < out_floats)
            *reinterpret_cast<float4*>(out + fi) = res[p];
    }
}

// ---------------- launch ----------------
extern "C" void kernel_launch(void* const* d_in, const int* in_sizes, int n_in,
                              void* d_out, int out_size)
{
    const float* P[17];
    long long    S[17];
    for (int i = 0; i < 17; ++i) {
        P[i] = (i < n_in) ? (const float*)d_in[i] : nullptr;
        S[i] = (i < n_in) ? (long long)in_sizes[i] : 0;
    }
    const float *ayr = P[0],  *ayi = P[1];
    const float *zr  = P[2],  *zi  = P[3];
    const float *vr  = P[4],  *vi  = P[5];
    const float *wdr = P[6],  *wdi = P[7];
    const float *reta= P[8];
    const float *Wrw = P[9],  *Wrb = P[10];
    const float *Urw = P[11], *Urb = P[12];
    const float *Wiw = P[13], *Wib = P[14];
    const float *Uiw = P[15], *Uib = P[16];

    long long BNl = S[0];
    if (BNl > (long long)B_MAX * N_DIM) BNl = (long long)B_MAX * N_DIM;
    int BN = (int)BNl;
    int B  = BN / N_DIM;
    if (B < 1) B = 1;

    int ntiles = (B + BM - 1) / BM;
    int gx = (ntiles < GRIDX) ? ntiles : GRIDX;

    cudaFuncSetAttribute(gate_gemm_wmma,
                         cudaFuncAttributeMaxDynamicSharedMemorySize, SMEM_TOTAL);

    gate_gemm_wmma<<<gx, NTHR, SMEM_TOTAL>>>(zr, vr, Wrw, Urw, Wrb, Urb,
                                             S[9], S[10], B, ntiles, gx, 0);
    gate_gemm_wmma<<<gx, NTHR, SMEM_TOTAL>>>(zi, vi, Wiw, Uiw, Wib, Uib,
                                             S[9], S[10], B, ntiles, gx, 1);

    int nquads = BN >> 2;
    int fblocks = (nquads + 255) / 256;
    fuse_kernel<<<fblocks, 256>>>(ayr, ayi, zr, zi, vr, vi, wdr, wdi, reta,
                                  (float*)d_out, BN,
                                  S[8], (long long)out_size);
}

// round 16
// speedup vs baseline: 4.5827x; 1.3414x over previous
#include <cuda_runtime.h>
#include <cuda_bf16.h>
#include <mma.h>
#include <math.h>
#include <stdint.h>

using namespace nvcuda;

// ---------------- problem constants ----------------
#define N_DIM 121
#define K_RAW 242
#define K_BIAS 242           // bias folded in as k-column 242
#define KP    256            // padded K (16 wmma k-steps)
#define LDA   264            // smem leading dim (bf16), conflict-padded
#define BM    64             // rows per tile
#define GPITCH 128           // g_scratch row pitch (floats)
#define B_MAX 32768
#define GRIDX 74             // blocks per plane (x2 planes = 148 = one wave)
#define NTHR  1024

// g scratch, padded rows so wmma can store 16x16 tiles directly.
__device__ float g_scratch[2][(long long)B_MAX * GPITCH];

__device__ __forceinline__ float safe_ld(const float* p, long long idx, long long sz) {
    return (p != nullptr && idx >= 0 && idx < sz) ? p[idx] : 0.f;
}

// ---------------- smem layout (bytes) ----------------
#define W_BYTES  (128 * LDA * 2)
#define A_BYTES  (BM * LDA * 2)
#define OFF_WHI  0
#define OFF_WLO  (OFF_WHI + W_BYTES)
#define OFF_AHI  (OFF_WLO + W_BYTES)
#define OFF_ALO  (OFF_AHI + A_BYTES)
#define SMEM_TOTAL (OFF_ALO + A_BYTES)        // 202,752 B

// ---------------- persistent WMMA gate GEMM + sigmoid (both planes) ----------------
// g[b,n] = sigmoid( [z|v|1][b,:] @ [W|U|bias][n,:]^T );  blockIdx.y = plane
extern "C" __global__ void __launch_bounds__(NTHR, 1)
gate_gemm_wmma(const float* __restrict__ z_r, const float* __restrict__ v_r,
               const float* __restrict__ Wr,  const float* __restrict__ Ur,
               const float* __restrict__ Wrb, const float* __restrict__ Urb,
               const float* __restrict__ z_i, const float* __restrict__ v_i,
               const float* __restrict__ Wi,  const float* __restrict__ Ui,
               const float* __restrict__ Wib, const float* __restrict__ Uib,
               long long sz_w, long long sz_b,
               int Brows, int ntiles, int stride)
{
    extern __shared__ char smem[];
    __nv_bfloat16* Whi = reinterpret_cast<__nv_bfloat16*>(smem + OFF_WHI);
    __nv_bfloat16* Wlo = reinterpret_cast<__nv_bfloat16*>(smem + OFF_WLO);
    __nv_bfloat16* Ahi = reinterpret_cast<__nv_bfloat16*>(smem + OFF_AHI);
    __nv_bfloat16* Alo = reinterpret_cast<__nv_bfloat16*>(smem + OFF_ALO);

    const int plane = blockIdx.y;
    const float* Z  = plane ? z_i : z_r;
    const float* V  = plane ? v_i : v_r;
    const float* W  = plane ? Wi  : Wr;
    const float* U  = plane ? Ui  : Ur;
    const float* Wb = plane ? Wib : Wrb;
    const float* Ub = plane ? Uib : Urb;

    const int tid = threadIdx.x;

    // --- stage weights ONCE: [n][k] = W | U | bias | 0, bf16 hi/lo split ---
    for (int idx = tid; idx < 128 * KP; idx += NTHR) {
        int n = idx >> 8;
        int k = idx & 255;
        float val = 0.f;
        if (n < N_DIM) {
            if (k < N_DIM)        val = safe_ld(W, (long long)n * N_DIM + k, sz_w);
            else if (k < K_RAW)   val = safe_ld(U, (long long)n * N_DIM + (k - N_DIM), sz_w);
            else if (k == K_BIAS) val = safe_ld(Wb, n, sz_b) + safe_ld(Ub, n, sz_b);
        }
        __nv_bfloat16 h = __float2bfloat16(val);
        __nv_bfloat16 l = __float2bfloat16(val - __bfloat162float(h));
        Whi[n * LDA + k] = h;
        Wlo[n * LDA + k] = l;
    }
    // zero the A pad k-columns once (242..255; 242 rewritten with 1.0 below)
    for (int idx = tid; idx < BM; idx += NTHR) {
        for (int k = K_RAW; k < KP; ++k) {
            Ahi[idx * LDA + k] = __float2bfloat16(0.f);
            Alo[idx * LDA + k] = __float2bfloat16(0.f);
        }
    }

    const int wid  = tid >> 5;
    const int wm   = wid & 3;        // 4 groups of 16 rows
    const int wn   = wid >> 2;       // 8 groups of 16 cols
    const int kcol = tid & 255;      // staged k column
    const int rq   = tid >> 8;       // row quarter: rows rq*16 .. rq*16+15

    // --- register prefetch: rbuf[i] = A[tile*64 + rq*16 + i][kcol] ---
    float rbuf[16];
    auto prefetch = [&](int tile) {
        if (kcol >= K_RAW) return;
        const float* src  = (kcol < N_DIM) ? Z : V;
        const int    koff = (kcol < N_DIM) ? kcol : (kcol - N_DIM);
#pragma unroll
        for (int i = 0; i < 16; ++i) {
            long long row = (long long)tile * BM + rq * 16 + i;
            rbuf[i] = (row < Brows) ? src[row * N_DIM + koff] : 0.f;
        }
    };

    float* gdst = g_scratch[plane];
    int t = blockIdx.x;
    if (t < ntiles) prefetch(t);
    __syncthreads();   // weights + A-pad visible

    for (; t < ntiles; t += stride) {
        // convert prefetched A -> smem bf16 hi/lo (k column kcol, 16 rows)
        if (kcol < K_RAW) {
#pragma unroll
            for (int i = 0; i < 16; ++i) {
                float v = rbuf[i];
                __nv_bfloat16 h = __float2bfloat16(v);
                __nv_bfloat16 l = __float2bfloat16(v - __bfloat162float(h));
                int r = rq * 16 + i;
                Ahi[r * LDA + kcol] = h;
                Alo[r * LDA + kcol] = l;
            }
        } else if (kcol == K_BIAS) {
#pragma unroll
            for (int i = 0; i < 16; ++i) {
                int r = rq * 16 + i;
                Ahi[r * LDA + kcol] = __float2bfloat16(1.f);
                Alo[r * LDA + kcol] = __float2bfloat16(0.f);
            }
        }
        __syncthreads();

        // issue next tile's LDGs now; latency hidden behind the mma loop
        if (t + stride < ntiles) prefetch(t + stride);

        // --- mma: 3-term bf16 split, 16 k-steps, one 16x16 tile per warp ---
        wmma::fragment<wmma::accumulator, 16, 16, 16, float> c;
        wmma::fill_fragment(c, 0.f);

        const int ncol = wn * 16;
#pragma unroll
        for (int ks = 0; ks < 16; ++ks) {
            int k0 = ks * 16;
            wmma::fragment<wmma::matrix_a, 16, 16, 16, __nv_bfloat16, wmma::row_major> ah, al;
            wmma::fragment<wmma::matrix_b, 16, 16, 16, __nv_bfloat16, wmma::col_major> bh, bl;
            wmma::load_matrix_sync(ah, Ahi + (wm * 16) * LDA + k0, LDA);
            wmma::load_matrix_sync(al, Alo + (wm * 16) * LDA + k0, LDA);
            wmma::load_matrix_sync(bh, Whi + ncol * LDA + k0, LDA);
            wmma::load_matrix_sync(bl, Wlo + ncol * LDA + k0, LDA);
            wmma::mma_sync(c, ah, bh, c);
            wmma::mma_sync(c, al, bh, c);
            wmma::mma_sync(c, ah, bl, c);
        }

        // --- sigmoid on fragment (layout-agnostic), store direct to g_scratch ---
#pragma unroll
        for (int e = 0; e < c.num_elements; ++e)
            c.x[e] = 1.f / (1.f + __expf(-c.x[e]));
        long long grow0 = (long long)t * BM + wm * 16;
        wmma::store_matrix_sync(gdst + grow0 * GPITCH + ncol, c,
                                GPITCH, wmma::mem_row_major);
        __syncthreads();   // all A reads done before next convert overwrites
    }
}

// ---------------- fused complex epilogue kernel (x4 vectorized) ----------------
// Output: six BN-float planes: [x_re][z_re][v_re][x_im][z_im][v_im]
extern "C" __global__ void __launch_bounds__(256)
fuse_kernel(const float* __restrict__ ayr, const float* __restrict__ ayi,
            const float* __restrict__ zr,  const float* __restrict__ zi,
            const float* __restrict__ vr,  const float* __restrict__ vi,
            const float* __restrict__ wdr, const float* __restrict__ wdi,
            const float* __restrict__ raw_eta,
            float* __restrict__ out, int BN,
            long long sz_eta, long long out_floats)
{
    int q = blockIdx.x * blockDim.x + threadIdx.x;   // quad index
    int nquads = BN >> 2;
    if (q >= nquads) return;
    int idx0 = q << 2;

    float re  = safe_ld(raw_eta, 0, sz_eta);
    float eta = fmaxf(re, 0.f) + log1pf(__expf(-fabsf(re)));

    float4 zr4 = *reinterpret_cast<const float4*>(zr + idx0);
    float4 zi4 = *reinterpret_cast<const float4*>(zi + idx0);
    float4 vr4 = *reinterpret_cast<const float4*>(vr + idx0);
    float4 vi4 = *reinterpret_cast<const float4*>(vi + idx0);
    float4 ar4 = *reinterpret_cast<const float4*>(ayr + idx0);
    float4 ai4 = *reinterpret_cast<const float4*>(ayi + idx0);

    float4 oxr, oxi, ozr, ozi, ovr, ovi;
    float* pzr = &zr4.x; float* pzi = &zi4.x;
    float* pvr = &vr4.x; float* pvi = &vi4.x;
    float* par = &ar4.x; float* pai = &ai4.x;
    float* poxr = &oxr.x; float* poxi = &oxi.x;
    float* pozr = &ozr.x; float* pozi = &ozi.x;
    float* povr = &ovr.x; float* povi = &ovi.x;

#pragma unroll
    for (int e = 0; e < 4; ++e) {
        int idx = idx0 + e;
        unsigned row = (unsigned)idx / N_DIM;
        unsigned n   = (unsigned)idx - row * N_DIM;

        float zpr = pzr[e], zpi = pzi[e];
        float vpr = pvr[e], vpi = pvi[e];

        float nr = par[e] + eta * (zpr - vpr);
        float ni = pai[e] + eta * (zpi - vpi);
        float dr = wdr[n] + eta;
        float di = wdi[n];
        float inv = 1.f / (dr * dr + di * di);
        float xr = (nr * dr + ni * di) * inv;
        float xi = (ni * dr - nr * di) * inv;

        float ur = xr + vpr;
        float ui = xi + vpi;

        long long gidx = (long long)row * GPITCH + n;
        float gr = g_scratch[0][gidx];
        float gi = g_scratch[1][gidx];

        float zor = gr * ur - gi * ui + (1.f - gr) * zpr + gi * zpi;
        float zoi = gr * ui + gi * ur + (1.f - gr) * zpi - gi * zpr;

        poxr[e] = xr;  poxi[e] = xi;
        pozr[e] = zor; pozi[e] = zoi;
        povr[e] = vpr + xr - zor;
        povi[e] = vpi + xi - zoi;
    }

    float4 res[6] = {oxr, ozr, ovr, oxi, ozi, ovi};
#pragma unroll
    for (int p = 0; p < 6; ++p) {
        long long fi = (long long)p * BN + idx0;
        if (fi + 3 < out_floats)
            *reinterpret_cast<float4*>(out + fi) = res[p];
    }
}

// first launch in the cycle so ncu's fixed capture index lands on the GEMM.
extern "C" __global__ void dummy_probe() {}

// ---------------- launch ----------------
extern "C" void kernel_launch(void* const* d_in, const int* in_sizes, int n_in,
                              void* d_out, int out_size)
{
    const float* P[17];
    long long    S[17];
    for (int i = 0; i < 17; ++i) {
        P[i] = (i < n_in) ? (const float*)d_in[i] : nullptr;
        S[i] = (i < n_in) ? (long long)in_sizes[i] : 0;
    }
    const float *ayr = P[0],  *ayi = P[1];
    const float *zr  = P[2],  *zi  = P[3];
    const float *vr  = P[4],  *vi  = P[5];
    const float *wdr = P[6],  *wdi = P[7];
    const float *reta= P[8];
    const float *Wrw = P[9],  *Wrb = P[10];
    const float *Urw = P[11], *Urb = P[12];
    const float *Wiw = P[13], *Wib = P[14];
    const float *Uiw = P[15], *Uib = P[16];

    long long BNl = S[0];
    if (BNl > (long long)B_MAX * N_DIM) BNl = (long long)B_MAX * N_DIM;
    int BN = (int)BNl;
    int B  = BN / N_DIM;
    if (B < 1) B = 1;

    int ntiles = (B + BM - 1) / BM;
    int gx = (ntiles < GRIDX) ? ntiles : GRIDX;

    cudaFuncSetAttribute(gate_gemm_wmma,
                         cudaFuncAttributeMaxDynamicSharedMemorySize, SMEM_TOTAL);

    dummy_probe<<<1, 32>>>();

    dim3 ggrid(gx, 2);
    gate_gemm_wmma<<<ggrid, NTHR, SMEM_TOTAL>>>(
        zr, vr, Wrw, Urw, Wrb, Urb,
        zi, vi, Wiw, Uiw, Wib, Uib,
        S[9], S[10], B, ntiles, gx);

    int nquads = BN >> 2;
    int fblocks = (nquads + 255) / 256;
    fuse_kernel<<<fblocks, 256>>>(ayr, ayi, zr, zi, vr, vi, wdr, wdi, reta,
                                  (float*)d_out, BN,
                                  S[8], (long long)out_size);
}